// round 12
// baseline (speedup 1.0000x reference)
#include <cuda_runtime.h>
#include <cuda_fp16.h>
#include <cstdint>

// Problem constants
#define BATCH 4
#define SEQ   2048
#define HID   1024
#define NH    16
#define DK    64
#define MROWS (BATCH*SEQ)          // 8192
#define QKV_N (3*NH*DK)            // 3072
#define K2G   512                  // K/2 (u32 half2 units) for both GEMMs
#define LOG2E 1.4426950408889634f

// fp16-packed scratch (u32 = half2)
__device__ uint32_t g_xh[(size_t)MROWS*K2G];        // x        [m][k2]
__device__ uint32_t g_w1h[(size_t)QKV_N*K2G];       // W1^T     [n][k2]
__device__ uint32_t g_w2h[(size_t)HID*K2G];         // W2^T     [n][k2]
__device__ uint32_t g_qh[(size_t)BATCH*NH*SEQ*32];  // [bh][s][d2]
__device__ uint32_t g_kh[(size_t)BATCH*NH*SEQ*32];  // [bh][s][d2]
__device__ uint32_t g_vh[(size_t)BATCH*NH*SEQ*32];  // [bh][s][d2] (trans-LDSM in attn)
__device__ uint32_t g_ctxh[(size_t)MROWS*K2G];      // [m][k2]

__device__ __forceinline__ uint32_t h2(float lo, float hi) {
    __half2 h = __floats2half2_rn(lo, hi);
    return *(uint32_t*)&h;
}
__device__ __forceinline__ uint32_t smem_u32(const void* p) {
    uint32_t a;
    asm("{ .reg .u64 t; cvta.to.shared.u64 t, %1; cvt.u32.u64 %0, t; }"
        : "=r"(a) : "l"(p));
    return a;
}

#define MMA_F16(d, a0,a1,a2,a3, b0,b1) \
    asm volatile( \
        "mma.sync.aligned.m16n8k16.row.col.f32.f16.f16.f32 " \
        "{%0,%1,%2,%3}, {%4,%5,%6,%7}, {%8,%9}, {%0,%1,%2,%3};" \
        : "+f"((d)[0]), "+f"((d)[1]), "+f"((d)[2]), "+f"((d)[3]) \
        : "r"(a0), "r"(a1), "r"(a2), "r"(a3), "r"(b0), "r"(b1))

#define LDSM4(r0,r1,r2,r3, addr) \
    asm volatile("ldmatrix.sync.aligned.m8n8.x4.shared.b16 {%0,%1,%2,%3}, [%4];" \
        : "=r"(r0), "=r"(r1), "=r"(r2), "=r"(r3) : "r"(addr))

#define LDSM4T(r0,r1,r2,r3, addr) \
    asm volatile("ldmatrix.sync.aligned.m8n8.x4.trans.shared.b16 {%0,%1,%2,%3}, [%4];" \
        : "=r"(r0), "=r"(r1), "=r"(r2), "=r"(r3) : "r"(addr))

#define CP16(dst, src) \
    asm volatile("cp.async.cg.shared.global [%0], [%1], 16;" :: "r"(dst), "l"(src))
#define CP_COMMIT()  asm volatile("cp.async.commit_group;")
#define CP_WAIT(n)   asm volatile("cp.async.wait_group %0;" :: "n"(n))

// exp2 on packed half2
__device__ __forceinline__ uint32_t ex2h2(float t0, float t1) {
    uint32_t r, t = h2(t0, t1);
    asm("ex2.approx.f16x2 %0, %1;" : "=r"(r) : "r"(t));
    return r;
}

// ---------------------------------------------------------------------------
// Converters
// ---------------------------------------------------------------------------
__global__ void cvt_x(const float* __restrict__ x)
{
    size_t i = (size_t)blockIdx.x * 256 + threadIdx.x;
    float4 v = ((const float4*)x)[i];
    ((uint2*)g_xh)[i] = make_uint2(h2(v.x, v.y), h2(v.z, v.w));
}

__global__ void cvt_w(const float* __restrict__ W, int Ncols, int which)
{
    uint32_t* dst = which ? g_w2h : g_w1h;
    __shared__ float t[32][33];
    int n0 = blockIdx.x * 32, k0 = blockIdx.y * 32;
    int tx = threadIdx.x, ty = threadIdx.y;
#pragma unroll
    for (int r = ty; r < 32; r += 8)
        t[r][tx] = W[(size_t)(k0 + r) * Ncols + n0 + tx];
    __syncthreads();
#pragma unroll
    for (int r = ty; r < 32; r += 8)
        if (tx < 16)
            dst[(size_t)(n0 + r) * K2G + (k0 >> 1) + tx] =
                h2(t[2 * tx][r], t[2 * tx + 1][r]);
}

// ---------------------------------------------------------------------------
// fp16 GEMM: BM=BN=128, BK=32, 256 thr (8 warps 2x4, warp tile 64x32),
// 3-stage cp.async pipeline + ldmatrix. Chunk order staggered by warp
// parity (even warps 0,1; odd warps 1,0) to overlap LDSM and HMMA phases
// SM-wide.
// mode 0: A=g_xh, B=g_w1h, epilogue q/k/v interleaved (q*0.125).
// mode 1: A=g_ctxh, B=g_w2h, fp32 C.
// ---------------------------------------------------------------------------
#define GEMM_STAGE_U32 5120
#define GEMM_SMEM_BYTES (3*GEMM_STAGE_U32*4)

__global__ __launch_bounds__(256, 2)
void mma_gemm(const float* __restrict__ bias, float* __restrict__ C,
              int N, int mode)
{
    extern __shared__ uint32_t gsm[];

    const uint32_t* Ah = mode ? g_ctxh : g_xh;
    const uint32_t* Bh = mode ? g_w2h : g_w1h;

    const int tid = threadIdx.x;
    const int lane = tid & 31;
    const int wid = tid >> 5;
    const int wm = (wid & 1) * 64;
    const int wn = (wid >> 1) * 32;
    const int rowBase = blockIdx.y * 128;
    const int colBase = blockIdx.x * 128;
    const int wpar = wid & 1;          // chunk-order stagger

    const int arow = ((lane >> 3) & 1) * 8 + (lane & 7);
    const int acol = ((lane >> 4) & 1) * 4;
    const int brow = ((lane >> 4) & 1) * 8 + (lane & 7);
    const int bcol = ((lane >> 3) & 1) * 4;

    // cp.async: A 512 chunks (2/thr), B 512 chunks (2/thr)
    const int cr = tid >> 2;           // 0..63
    const int co = (tid & 3) * 4;
    const uint32_t sbase = smem_u32(gsm);
    const uint32_t dA0 = sbase + (cr * 20 + co) * 4;
    const uint32_t dA1 = sbase + ((cr + 64) * 20 + co) * 4;
    const uint32_t dB0 = sbase + (2560 + cr * 20 + co) * 4;
    const uint32_t dB1 = sbase + (2560 + (cr + 64) * 20 + co) * 4;

    float acc[4][4][4];
#pragma unroll
    for (int i = 0; i < 4; i++)
#pragma unroll
        for (int j = 0; j < 4; j++)
#pragma unroll
            for (int r = 0; r < 4; r++) acc[i][j][r] = 0.f;

    const int KT = 32;
    auto prefetch = [&](int st, int kt) {
        if (kt < KT) {
            uint32_t so = st * GEMM_STAGE_U32 * 4;
            const uint32_t* As = Ah + (size_t)(rowBase + cr) * K2G + kt * 16 + co;
            const uint32_t* Bs = Bh + (size_t)(colBase + cr) * K2G + kt * 16 + co;
            CP16(dA0 + so, As);
            CP16(dA1 + so, As + (size_t)64 * K2G);
            CP16(dB0 + so, Bs);
            CP16(dB1 + so, Bs + (size_t)64 * K2G);
        }
        CP_COMMIT();
    };

    prefetch(0, 0); prefetch(1, 1);

    for (int kt = 0; kt < KT; kt++) {
        const int st = kt - (kt / 3) * 3;
        CP_WAIT(1);
        __syncthreads();
        {
            int nx = kt + 2;
            prefetch(nx - (nx / 3) * 3, nx);
        }

        const uint32_t sa = sbase + (st * GEMM_STAGE_U32) * 4;
        const uint32_t sb = sa + 2560 * 4;
#pragma unroll
        for (int c = 0; c < 2; c++) {
            const int cc = c ^ wpar;                 // staggered chunk order
            uint32_t af[4][4], bf[4][2];
#pragma unroll
            for (int mf = 0; mf < 4; mf++)
                LDSM4(af[mf][0], af[mf][1], af[mf][2], af[mf][3],
                      sa + ((wm + mf * 16 + arow) * 20 + cc * 8 + acol) * 4);
#pragma unroll
            for (int np = 0; np < 2; np++)
                LDSM4(bf[2*np][0], bf[2*np][1], bf[2*np+1][0], bf[2*np+1][1],
                      sb + ((wn + np * 16 + brow) * 20 + cc * 8 + bcol) * 4);
#pragma unroll
            for (int mf = 0; mf < 4; mf++)
#pragma unroll
                for (int nf = 0; nf < 4; nf++)
                    MMA_F16(acc[mf][nf], af[mf][0], af[mf][1], af[mf][2], af[mf][3],
                            bf[nf][0], bf[nf][1]);
        }
    }

    const int egr = lane >> 2;
    const int elc = lane & 3;
#pragma unroll
    for (int mf = 0; mf < 4; mf++) {
#pragma unroll
        for (int nf = 0; nf < 4; nf++) {
            int m0 = rowBase + wm + mf * 16 + egr;
            int n0 = colBase + wn + nf * 8 + elc * 2;
            float bi0 = bias[n0], bi1 = bias[n0 + 1];
            if (mode == 0) {
                int qkv = n0 >> 10;
                int h = (n0 >> 6) & (NH - 1);
                int d2 = (n0 & 63) >> 1;
                float sc = (qkv == 0) ? 0.125f : 1.f;
                uint32_t* dst = (qkv == 0) ? g_qh : (qkv == 1) ? g_kh : g_vh;
#pragma unroll
                for (int half = 0; half < 2; half++) {
                    int m = m0 + half * 8;
                    int bb = m >> 11, ss = m & (SEQ - 1);
                    dst[(((size_t)bb * NH + h) * SEQ + ss) * 32 + d2] =
                        h2((acc[mf][nf][half*2+0] + bi0) * sc,
                           (acc[mf][nf][half*2+1] + bi1) * sc);
                }
            } else {
#pragma unroll
                for (int half = 0; half < 2; half++) {
                    int m = m0 + half * 8;
                    float* p = C + (size_t)m * N + n0;
                    p[0] = acc[mf][nf][half*2+0] + bi0;
                    p[1] = acc[mf][nf][half*2+1] + bi1;
                }
            }
        }
    }
}

// ---------------------------------------------------------------------------
// fp16 flash attention: 3-stage cp.async, ldmatrix (V via ldmatrix.trans),
// register softmax with ex2.approx.f16x2. Chunk order staggered by wid.
// 128 thr = 4 warps; warp = 32 q x 64; BQ=128, BK=64, 32 tiles.
// smem u32: Qs[128][36] | Ks[3][64][36] | Vs[3][64][36] = 73728 B
// ---------------------------------------------------------------------------
#define ATTN_SMEM_BYTES ((4608 + 3*2304 + 3*2304) * 4)

__global__ __launch_bounds__(128, 2)
void attn_mma()
{
    extern __shared__ uint32_t sm[];
    const uint32_t qsb = smem_u32(sm);
    const uint32_t ksb = qsb + 4608 * 4;
    const uint32_t vsb = ksb + 3 * 2304 * 4;

    const int tid = threadIdx.x;
    const int lane = tid & 31;
    const int wid = tid >> 5;
    const int gr = lane >> 2;
    const int lc = lane & 3;
    const int q0 = blockIdx.x * 128;
    const int bh = blockIdx.y;
    const int wrow = wid * 32;

    const int arow = ((lane >> 3) & 1) * 8 + (lane & 7);
    const int acol = ((lane >> 4) & 1) * 4;
    const int brow = ((lane >> 4) & 1) * 8 + (lane & 7);
    const int bcol = ((lane >> 3) & 1) * 4;
    // trans-LDSM lane addressing for V (row = s, halves col = d)
    const int vrow = ((lane >> 3) & 1) * 8 + (lane & 7);
    const int vcolh = (lane >> 4) * 8;

    const uint32_t* Kg = g_kh + (size_t)bh * SEQ * 32;
    const uint32_t* Vg = g_vh + (size_t)bh * SEQ * 32;

    // Q tile once
    {
        const uint4* Qg4 = (const uint4*)(g_qh + ((size_t)bh * SEQ + q0) * 32);
#pragma unroll
        for (int it = 0; it < 8; it++) {
            int i = tid + it * 128;
            int r = i >> 3, c = i & 7;
            *(uint4*)&sm[r * 36 + c * 4] = Qg4[r * 8 + c];
        }
    }

    const int NT = SEQ / 64;
    auto prefetch = [&](int st, int kt) {
        if (kt < NT) {
#pragma unroll
            for (int i = 0; i < 4; i++) {
                int c = tid + i * 128;
                int row = c >> 3, off = (c & 7) * 4;
                CP16(ksb + (st * 2304 + row * 36 + off) * 4,
                     Kg + (size_t)(kt * 64 + row) * 32 + off);
                CP16(vsb + (st * 2304 + row * 36 + off) * 4,
                     Vg + (size_t)(kt * 64 + row) * 32 + off);
            }
        }
        CP_COMMIT();
    };

    float o[2][8][4];
#pragma unroll
    for (int mf = 0; mf < 2; mf++)
#pragma unroll
        for (int nf = 0; nf < 8; nf++)
#pragma unroll
            for (int r = 0; r < 4; r++) o[mf][nf][r] = 0.f;
    float mrow[2][2] = { {-1e30f, -1e30f}, {-1e30f, -1e30f} };
    float lrow[2][2] = { {0.f, 0.f}, {0.f, 0.f} };

    prefetch(0, 0); prefetch(1, 1);

    for (int kt = 0; kt < NT; kt++) {
        const int st = kt - (kt / 3) * 3;
        CP_WAIT(1);
        __syncthreads();
        {
            int nx = kt + 2;
            prefetch(nx - (nx / 3) * 3, nx);
        }

        // S = Q @ K^T  (chunk order staggered per warp)
        float ps[2][8][4];
#pragma unroll
        for (int mf = 0; mf < 2; mf++)
#pragma unroll
            for (int nf = 0; nf < 8; nf++)
#pragma unroll
                for (int r = 0; r < 4; r++) ps[mf][nf][r] = 0.f;

#pragma unroll
        for (int ch = 0; ch < 4; ch++) {
            const int cc = (ch + wid) & 3;
            uint32_t a[2][4], bK[8][2];
#pragma unroll
            for (int mf = 0; mf < 2; mf++)
                LDSM4(a[mf][0], a[mf][1], a[mf][2], a[mf][3],
                      qsb + ((wrow + mf * 16 + arow) * 36 + cc * 8 + acol) * 4);
#pragma unroll
            for (int np = 0; np < 4; np++)
                LDSM4(bK[2*np][0], bK[2*np][1], bK[2*np+1][0], bK[2*np+1][1],
                      ksb + (st * 2304 + (np * 16 + brow) * 36 + cc * 8 + bcol) * 4);
#pragma unroll
            for (int nf = 0; nf < 8; nf++) {
                MMA_F16(ps[0][nf], a[0][0], a[0][1], a[0][2], a[0][3],
                        bK[nf][0], bK[nf][1]);
                MMA_F16(ps[1][nf], a[1][0], a[1][1], a[1][2], a[1][3],
                        bK[nf][0], bK[nf][1]);
            }
        }

        // Online softmax -> fp16 P via ex2.f16x2
        uint32_t pp[2][8][2];
#pragma unroll
        for (int mf = 0; mf < 2; mf++) {
#pragma unroll
            for (int h = 0; h < 2; h++) {
                float mx = -1e30f;
#pragma unroll
                for (int nf = 0; nf < 8; nf++)
                    mx = fmaxf(mx, fmaxf(ps[mf][nf][2*h], ps[mf][nf][2*h+1]));
                mx = fmaxf(mx, __shfl_xor_sync(0xffffffffu, mx, 1));
                mx = fmaxf(mx, __shfl_xor_sync(0xffffffffu, mx, 2));
                float mnew = fmaxf(mrow[mf][h], mx);
                float corr = __expf(mrow[mf][h] - mnew);
                float mL = mnew * LOG2E;
                float sum = 0.f;
#pragma unroll
                for (int nf = 0; nf < 8; nf++) {
                    float t0 = fmaf(ps[mf][nf][2*h],   LOG2E, -mL);
                    float t1 = fmaf(ps[mf][nf][2*h+1], LOG2E, -mL);
                    uint32_t ph = ex2h2(t0, t1);
                    pp[mf][nf][h] = ph;
                    float2 f = __half22float2(*(__half2*)&ph);
                    sum += f.x + f.y;
                }
                sum += __shfl_xor_sync(0xffffffffu, sum, 1);
                sum += __shfl_xor_sync(0xffffffffu, sum, 2);
                lrow[mf][h] = lrow[mf][h] * corr + sum;
                mrow[mf][h] = mnew;
#pragma unroll
                for (int nf = 0; nf < 8; nf++) {
                    o[mf][nf][2*h]   *= corr;
                    o[mf][nf][2*h+1] *= corr;
                }
            }
        }

        // O += P @ V  (V [s][d] tile, B-frags via ldmatrix.trans; staggered)
#pragma unroll
        for (int kf = 0; kf < 4; kf++) {
            const int kk = (kf + wid) & 3;
            uint32_t bV[8][2];
#pragma unroll
            for (int np = 0; np < 4; np++)
                LDSM4T(bV[2*np][0], bV[2*np][1], bV[2*np+1][0], bV[2*np+1][1],
                       vsb + (st * 2304 + (kk * 16 + vrow) * 36) * 4
                           + (np * 16 + vcolh) * 2);
#pragma unroll
            for (int nf = 0; nf < 8; nf++) {
                MMA_F16(o[0][nf], pp[0][2*kk][0], pp[0][2*kk][1],
                        pp[0][2*kk+1][0], pp[0][2*kk+1][1], bV[nf][0], bV[nf][1]);
                MMA_F16(o[1][nf], pp[1][2*kk][0], pp[1][2*kk][1],
                        pp[1][2*kk+1][0], pp[1][2*kk+1][1], bV[nf][0], bV[nf][1]);
            }
        }
    }

    // epilogue -> g_ctxh fp16-packed [m][512]
    const int bb = bh >> 4;
    const int h_head = bh & (NH - 1);
#pragma unroll
    for (int mf = 0; mf < 2; mf++) {
#pragma unroll
        for (int half = 0; half < 2; half++) {
            float inv = 1.f / lrow[mf][half];
            int qrow = q0 + wrow + mf * 16 + half * 8 + gr;
            uint32_t* base = g_ctxh + ((size_t)bb * SEQ + qrow) * K2G
                           + h_head * 32 + lc;
#pragma unroll
            for (int nf = 0; nf < 8; nf++)
                base[nf * 4] = h2(o[mf][nf][2*half] * inv,
                                  o[mf][nf][2*half+1] * inv);
        }
    }
}

// ---------------------------------------------------------------------------
extern "C" void kernel_launch(void* const* d_in, const int* in_sizes, int n_in,
                              void* d_out, int out_size)
{
    const float* x  = (const float*)d_in[0];
    const float* W1 = (const float*)d_in[1];
    const float* b1 = (const float*)d_in[2];
    const float* W2 = (const float*)d_in[3];
    const float* b2 = (const float*)d_in[4];
    float* out = (float*)d_out;

    // 0) converters
    cvt_x<<<MROWS * HID / 4 / 256, 256>>>(x);
    cvt_w<<<dim3(QKV_N / 32, HID / 32), dim3(32, 8)>>>(W1, QKV_N, 0);
    cvt_w<<<dim3(HID / 32, HID / 32), dim3(32, 8)>>>(W2, HID, 1);

    cudaFuncSetAttribute(mma_gemm,
                         cudaFuncAttributeMaxDynamicSharedMemorySize,
                         GEMM_SMEM_BYTES);
    cudaFuncSetAttribute(attn_mma,
                         cudaFuncAttributeMaxDynamicSharedMemorySize,
                         ATTN_SMEM_BYTES);

    // 1) QKV projection -> q/k/v interleaved, q pre-scaled
    mma_gemm<<<dim3(QKV_N / 128, MROWS / 128), 256, GEMM_SMEM_BYTES>>>(
        b1, nullptr, QKV_N, 0);

    // 2) flash attention -> g_ctxh
    attn_mma<<<dim3(SEQ / 128, BATCH * NH), 128, ATTN_SMEM_BYTES>>>();

    // 3) output projection -> fp32 out
    mma_gemm<<<dim3(HID / 128, MROWS / 128), 256, GEMM_SMEM_BYTES>>>(
        b2, out, HID, 1);
}

// round 13
// speedup vs baseline: 1.1026x; 1.1026x over previous
#include <cuda_runtime.h>
#include <cuda_fp16.h>
#include <cstdint>

// Problem constants
#define BATCH 4
#define SEQ   2048
#define HID   1024
#define NH    16
#define DK    64
#define MROWS (BATCH*SEQ)          // 8192
#define QKV_N (3*NH*DK)            // 3072
#define K2G   512                  // K/2 (u32 half2 units) for both GEMMs
#define LOG2E 1.4426950408889634f

// fp16-packed scratch (u32 = half2)
__device__ uint32_t g_xh[(size_t)MROWS*K2G];        // x        [m][k2]
__device__ uint32_t g_w1h[(size_t)QKV_N*K2G];       // W1^T     [n][k2]
__device__ uint32_t g_w2h[(size_t)HID*K2G];         // W2^T     [n][k2]
__device__ uint32_t g_qh[(size_t)BATCH*NH*SEQ*32];  // [bh][s][d2]
__device__ uint32_t g_kh[(size_t)BATCH*NH*SEQ*32];  // [bh][s][d2]
__device__ uint32_t g_vh[(size_t)BATCH*NH*SEQ*32];  // [bh][s][d2] (trans-LDSM in attn)
__device__ uint32_t g_ctxh[(size_t)MROWS*K2G];      // [m][k2]

__device__ __forceinline__ uint32_t h2(float lo, float hi) {
    __half2 h = __floats2half2_rn(lo, hi);
    return *(uint32_t*)&h;
}
__device__ __forceinline__ uint32_t smem_u32(const void* p) {
    uint32_t a;
    asm("{ .reg .u64 t; cvta.to.shared.u64 t, %1; cvt.u32.u64 %0, t; }"
        : "=r"(a) : "l"(p));
    return a;
}

#define MMA_F16(d, a0,a1,a2,a3, b0,b1) \
    asm volatile( \
        "mma.sync.aligned.m16n8k16.row.col.f32.f16.f16.f32 " \
        "{%0,%1,%2,%3}, {%4,%5,%6,%7}, {%8,%9}, {%0,%1,%2,%3};" \
        : "+f"((d)[0]), "+f"((d)[1]), "+f"((d)[2]), "+f"((d)[3]) \
        : "r"(a0), "r"(a1), "r"(a2), "r"(a3), "r"(b0), "r"(b1))

#define LDSM4(r0,r1,r2,r3, addr) \
    asm volatile("ldmatrix.sync.aligned.m8n8.x4.shared.b16 {%0,%1,%2,%3}, [%4];" \
        : "=r"(r0), "=r"(r1), "=r"(r2), "=r"(r3) : "r"(addr))

#define LDSM4T(r0,r1,r2,r3, addr) \
    asm volatile("ldmatrix.sync.aligned.m8n8.x4.trans.shared.b16 {%0,%1,%2,%3}, [%4];" \
        : "=r"(r0), "=r"(r1), "=r"(r2), "=r"(r3) : "r"(addr))

#define CP16(dst, src) \
    asm volatile("cp.async.cg.shared.global [%0], [%1], 16;" :: "r"(dst), "l"(src))
#define CP_COMMIT()  asm volatile("cp.async.commit_group;")
#define CP_WAIT(n)   asm volatile("cp.async.wait_group %0;" :: "n"(n))

// exp2 on packed half2
__device__ __forceinline__ uint32_t ex2h2(float t0, float t1) {
    uint32_t r, t = h2(t0, t1);
    asm("ex2.approx.f16x2 %0, %1;" : "=r"(r) : "r"(t));
    return r;
}

// ---------------------------------------------------------------------------
// Converters
// ---------------------------------------------------------------------------
__global__ void cvt_x(const float* __restrict__ x)
{
    size_t i = (size_t)blockIdx.x * 256 + threadIdx.x;
    float4 v = ((const float4*)x)[i];
    ((uint2*)g_xh)[i] = make_uint2(h2(v.x, v.y), h2(v.z, v.w));
}

__global__ void cvt_w(const float* __restrict__ W, int Ncols, int which)
{
    uint32_t* dst = which ? g_w2h : g_w1h;
    __shared__ float t[32][33];
    int n0 = blockIdx.x * 32, k0 = blockIdx.y * 32;
    int tx = threadIdx.x, ty = threadIdx.y;
#pragma unroll
    for (int r = ty; r < 32; r += 8)
        t[r][tx] = W[(size_t)(k0 + r) * Ncols + n0 + tx];
    __syncthreads();
#pragma unroll
    for (int r = ty; r < 32; r += 8)
        if (tx < 16)
            dst[(size_t)(n0 + r) * K2G + (k0 >> 1) + tx] =
                h2(t[2 * tx][r], t[2 * tx + 1][r]);
}

// ---------------------------------------------------------------------------
// fp16 GEMM: BM=BN=128, BK=64, 256 thr (8 warps 2x4, warp tile 64x32),
// 3-stage cp.async pipeline + ldmatrix. 64 MMA : 24 LDSM per warp between
// barriers; warp-parity chunk swap for phase drift.
// Stage (u32): A 128x36 | B 128x36 = 9216; 3 stages = 110592 B.
// mode 0: A=g_xh, B=g_w1h, epilogue q/k/v interleaved (q*0.125).
// mode 1: A=g_ctxh, B=g_w2h, fp32 C.
// ---------------------------------------------------------------------------
#define GEMM_STAGE_U32 9216
#define GEMM_SMEM_BYTES (3*GEMM_STAGE_U32*4)

__global__ __launch_bounds__(256, 2)
void mma_gemm(const float* __restrict__ bias, float* __restrict__ C,
              int N, int mode)
{
    extern __shared__ uint32_t gsm[];

    const uint32_t* Ah = mode ? g_ctxh : g_xh;
    const uint32_t* Bh = mode ? g_w2h : g_w1h;

    const int tid = threadIdx.x;
    const int lane = tid & 31;
    const int wid = tid >> 5;
    const int wm = (wid & 1) * 64;
    const int wn = (wid >> 1) * 32;
    const int rowBase = blockIdx.y * 128;
    const int colBase = blockIdx.x * 128;
    const int wpar = wid & 1;

    const int arow = ((lane >> 3) & 1) * 8 + (lane & 7);
    const int acol = ((lane >> 4) & 1) * 4;
    const int brow = ((lane >> 4) & 1) * 8 + (lane & 7);
    const int bcol = ((lane >> 3) & 1) * 4;

    const uint32_t sbase = smem_u32(gsm);

    float acc[4][4][4];
#pragma unroll
    for (int i = 0; i < 4; i++)
#pragma unroll
        for (int j = 0; j < 4; j++)
#pragma unroll
            for (int r = 0; r < 4; r++) acc[i][j][r] = 0.f;

    const int KT = 16;                  // 1024 / 64
    auto prefetch = [&](int st, int kt) {
        if (kt < KT) {
            uint32_t so = sbase + st * GEMM_STAGE_U32 * 4;
#pragma unroll
            for (int i = 0; i < 4; i++) {
                int idx = tid + i * 256;          // 0..1023
                int r = idx >> 3, off = (idx & 7) * 4;
                CP16(so + (r * 36 + off) * 4,
                     Ah + (size_t)(rowBase + r) * K2G + kt * 32 + off);
                CP16(so + (4608 + r * 36 + off) * 4,
                     Bh + (size_t)(colBase + r) * K2G + kt * 32 + off);
            }
        }
        CP_COMMIT();
    };

    prefetch(0, 0); prefetch(1, 1);

    for (int kt = 0; kt < KT; kt++) {
        const int st = kt - (kt / 3) * 3;
        CP_WAIT(1);
        __syncthreads();
        {
            int nx = kt + 2;
            prefetch(nx - (nx / 3) * 3, nx);
        }

        const uint32_t sa = sbase + (st * GEMM_STAGE_U32) * 4;
        const uint32_t sb = sa + 4608 * 4;
#pragma unroll
        for (int c = 0; c < 4; c++) {
            const int cc = c ^ wpar;
            uint32_t af[4][4], bf[4][2];
#pragma unroll
            for (int mf = 0; mf < 4; mf++)
                LDSM4(af[mf][0], af[mf][1], af[mf][2], af[mf][3],
                      sa + ((wm + mf * 16 + arow) * 36 + cc * 8 + acol) * 4);
#pragma unroll
            for (int np = 0; np < 2; np++)
                LDSM4(bf[2*np][0], bf[2*np][1], bf[2*np+1][0], bf[2*np+1][1],
                      sb + ((wn + np * 16 + brow) * 36 + cc * 8 + bcol) * 4);
#pragma unroll
            for (int mf = 0; mf < 4; mf++)
#pragma unroll
                for (int nf = 0; nf < 4; nf++)
                    MMA_F16(acc[mf][nf], af[mf][0], af[mf][1], af[mf][2], af[mf][3],
                            bf[nf][0], bf[nf][1]);
        }
    }

    const int egr = lane >> 2;
    const int elc = lane & 3;
#pragma unroll
    for (int mf = 0; mf < 4; mf++) {
#pragma unroll
        for (int nf = 0; nf < 4; nf++) {
            int m0 = rowBase + wm + mf * 16 + egr;
            int n0 = colBase + wn + nf * 8 + elc * 2;
            float bi0 = bias[n0], bi1 = bias[n0 + 1];
            if (mode == 0) {
                int qkv = n0 >> 10;
                int h = (n0 >> 6) & (NH - 1);
                int d2 = (n0 & 63) >> 1;
                float sc = (qkv == 0) ? 0.125f : 1.f;
                uint32_t* dst = (qkv == 0) ? g_qh : (qkv == 1) ? g_kh : g_vh;
#pragma unroll
                for (int half = 0; half < 2; half++) {
                    int m = m0 + half * 8;
                    int bb = m >> 11, ss = m & (SEQ - 1);
                    dst[(((size_t)bb * NH + h) * SEQ + ss) * 32 + d2] =
                        h2((acc[mf][nf][half*2+0] + bi0) * sc,
                           (acc[mf][nf][half*2+1] + bi1) * sc);
                }
            } else {
#pragma unroll
                for (int half = 0; half < 2; half++) {
                    int m = m0 + half * 8;
                    float* p = C + (size_t)m * N + n0;
                    p[0] = acc[mf][nf][half*2+0] + bi0;
                    p[1] = acc[mf][nf][half*2+1] + bi1;
                }
            }
        }
    }
}

// ---------------------------------------------------------------------------
// fp16 flash attention: 3-stage cp.async, ldmatrix (V via ldmatrix.trans),
// register softmax with ex2.approx.f16x2. Static loop order (no stagger —
// dynamic register indexing spills).
// 128 thr = 4 warps; warp = 32 q x 64; BQ=128, BK=64, 32 tiles.
// smem u32: Qs[128][36] | Ks[3][64][36] | Vs[3][64][36] = 73728 B
// ---------------------------------------------------------------------------
#define ATTN_SMEM_BYTES ((4608 + 3*2304 + 3*2304) * 4)

__global__ __launch_bounds__(128, 2)
void attn_mma()
{
    extern __shared__ uint32_t sm[];
    const uint32_t qsb = smem_u32(sm);
    const uint32_t ksb = qsb + 4608 * 4;
    const uint32_t vsb = ksb + 3 * 2304 * 4;

    const int tid = threadIdx.x;
    const int lane = tid & 31;
    const int wid = tid >> 5;
    const int gr = lane >> 2;
    const int lc = lane & 3;
    const int q0 = blockIdx.x * 128;
    const int bh = blockIdx.y;
    const int wrow = wid * 32;

    const int arow = ((lane >> 3) & 1) * 8 + (lane & 7);
    const int acol = ((lane >> 4) & 1) * 4;
    const int brow = ((lane >> 4) & 1) * 8 + (lane & 7);
    const int bcol = ((lane >> 3) & 1) * 4;
    // trans-LDSM lane addressing for V (row = s, halves col = d)
    const int vrow = ((lane >> 3) & 1) * 8 + (lane & 7);
    const int vcolh = (lane >> 4) * 8;

    const uint32_t* Kg = g_kh + (size_t)bh * SEQ * 32;
    const uint32_t* Vg = g_vh + (size_t)bh * SEQ * 32;

    // Q tile once
    {
        const uint4* Qg4 = (const uint4*)(g_qh + ((size_t)bh * SEQ + q0) * 32);
#pragma unroll
        for (int it = 0; it < 8; it++) {
            int i = tid + it * 128;
            int r = i >> 3, c = i & 7;
            *(uint4*)&sm[r * 36 + c * 4] = Qg4[r * 8 + c];
        }
    }

    const int NT = SEQ / 64;
    auto prefetch = [&](int st, int kt) {
        if (kt < NT) {
#pragma unroll
            for (int i = 0; i < 4; i++) {
                int c = tid + i * 128;
                int row = c >> 3, off = (c & 7) * 4;
                CP16(ksb + (st * 2304 + row * 36 + off) * 4,
                     Kg + (size_t)(kt * 64 + row) * 32 + off);
                CP16(vsb + (st * 2304 + row * 36 + off) * 4,
                     Vg + (size_t)(kt * 64 + row) * 32 + off);
            }
        }
        CP_COMMIT();
    };

    float o[2][8][4];
#pragma unroll
    for (int mf = 0; mf < 2; mf++)
#pragma unroll
        for (int nf = 0; nf < 8; nf++)
#pragma unroll
            for (int r = 0; r < 4; r++) o[mf][nf][r] = 0.f;
    float mrow[2][2] = { {-1e30f, -1e30f}, {-1e30f, -1e30f} };
    float lrow[2][2] = { {0.f, 0.f}, {0.f, 0.f} };

    prefetch(0, 0); prefetch(1, 1);

    for (int kt = 0; kt < NT; kt++) {
        const int st = kt - (kt / 3) * 3;
        CP_WAIT(1);
        __syncthreads();
        {
            int nx = kt + 2;
            prefetch(nx - (nx / 3) * 3, nx);
        }

        // S = Q @ K^T
        float ps[2][8][4];
#pragma unroll
        for (int mf = 0; mf < 2; mf++)
#pragma unroll
            for (int nf = 0; nf < 8; nf++)
#pragma unroll
                for (int r = 0; r < 4; r++) ps[mf][nf][r] = 0.f;

#pragma unroll
        for (int ch = 0; ch < 4; ch++) {
            uint32_t a[2][4], bK[8][2];
#pragma unroll
            for (int mf = 0; mf < 2; mf++)
                LDSM4(a[mf][0], a[mf][1], a[mf][2], a[mf][3],
                      qsb + ((wrow + mf * 16 + arow) * 36 + ch * 8 + acol) * 4);
#pragma unroll
            for (int np = 0; np < 4; np++)
                LDSM4(bK[2*np][0], bK[2*np][1], bK[2*np+1][0], bK[2*np+1][1],
                      ksb + (st * 2304 + (np * 16 + brow) * 36 + ch * 8 + bcol) * 4);
#pragma unroll
            for (int nf = 0; nf < 8; nf++) {
                MMA_F16(ps[0][nf], a[0][0], a[0][1], a[0][2], a[0][3],
                        bK[nf][0], bK[nf][1]);
                MMA_F16(ps[1][nf], a[1][0], a[1][1], a[1][2], a[1][3],
                        bK[nf][0], bK[nf][1]);
            }
        }

        // Online softmax -> fp16 P via ex2.f16x2
        uint32_t pp[2][8][2];
#pragma unroll
        for (int mf = 0; mf < 2; mf++) {
#pragma unroll
            for (int h = 0; h < 2; h++) {
                float mx = -1e30f;
#pragma unroll
                for (int nf = 0; nf < 8; nf++)
                    mx = fmaxf(mx, fmaxf(ps[mf][nf][2*h], ps[mf][nf][2*h+1]));
                mx = fmaxf(mx, __shfl_xor_sync(0xffffffffu, mx, 1));
                mx = fmaxf(mx, __shfl_xor_sync(0xffffffffu, mx, 2));
                float mnew = fmaxf(mrow[mf][h], mx);
                float corr = __expf(mrow[mf][h] - mnew);
                float mL = mnew * LOG2E;
                float sum = 0.f;
#pragma unroll
                for (int nf = 0; nf < 8; nf++) {
                    float t0 = fmaf(ps[mf][nf][2*h],   LOG2E, -mL);
                    float t1 = fmaf(ps[mf][nf][2*h+1], LOG2E, -mL);
                    uint32_t ph = ex2h2(t0, t1);
                    pp[mf][nf][h] = ph;
                    float2 f = __half22float2(*(__half2*)&ph);
                    sum += f.x + f.y;
                }
                sum += __shfl_xor_sync(0xffffffffu, sum, 1);
                sum += __shfl_xor_sync(0xffffffffu, sum, 2);
                lrow[mf][h] = lrow[mf][h] * corr + sum;
                mrow[mf][h] = mnew;
#pragma unroll
                for (int nf = 0; nf < 8; nf++) {
                    o[mf][nf][2*h]   *= corr;
                    o[mf][nf][2*h+1] *= corr;
                }
            }
        }

        // O += P @ V  (V [s][d] tile, B-frags via ldmatrix.trans)
#pragma unroll
        for (int kf = 0; kf < 4; kf++) {
            uint32_t bV[8][2];
#pragma unroll
            for (int np = 0; np < 4; np++)
                LDSM4T(bV[2*np][0], bV[2*np][1], bV[2*np+1][0], bV[2*np+1][1],
                       vsb + (st * 2304 + (kf * 16 + vrow) * 36) * 4
                           + (np * 16 + vcolh) * 2);
#pragma unroll
            for (int nf = 0; nf < 8; nf++) {
                MMA_F16(o[0][nf], pp[0][2*kf][0], pp[0][2*kf][1],
                        pp[0][2*kf+1][0], pp[0][2*kf+1][1], bV[nf][0], bV[nf][1]);
                MMA_F16(o[1][nf], pp[1][2*kf][0], pp[1][2*kf][1],
                        pp[1][2*kf+1][0], pp[1][2*kf+1][1], bV[nf][0], bV[nf][1]);
            }
        }
    }

    // epilogue -> g_ctxh fp16-packed [m][512]
    const int bb = bh >> 4;
    const int h_head = bh & (NH - 1);
#pragma unroll
    for (int mf = 0; mf < 2; mf++) {
#pragma unroll
        for (int half = 0; half < 2; half++) {
            float inv = 1.f / lrow[mf][half];
            int qrow = q0 + wrow + mf * 16 + half * 8 + gr;
            uint32_t* base = g_ctxh + ((size_t)bb * SEQ + qrow) * K2G
                           + h_head * 32 + lc;
#pragma unroll
            for (int nf = 0; nf < 8; nf++)
                base[nf * 4] = h2(o[mf][nf][2*half] * inv,
                                  o[mf][nf][2*half+1] * inv);
        }
    }
}

// ---------------------------------------------------------------------------
extern "C" void kernel_launch(void* const* d_in, const int* in_sizes, int n_in,
                              void* d_out, int out_size)
{
    const float* x  = (const float*)d_in[0];
    const float* W1 = (const float*)d_in[1];
    const float* b1 = (const float*)d_in[2];
    const float* W2 = (const float*)d_in[3];
    const float* b2 = (const float*)d_in[4];
    float* out = (float*)d_out;

    // 0) converters
    cvt_x<<<MROWS * HID / 4 / 256, 256>>>(x);
    cvt_w<<<dim3(QKV_N / 32, HID / 32), dim3(32, 8)>>>(W1, QKV_N, 0);
    cvt_w<<<dim3(HID / 32, HID / 32), dim3(32, 8)>>>(W2, HID, 1);

    cudaFuncSetAttribute(mma_gemm,
                         cudaFuncAttributeMaxDynamicSharedMemorySize,
                         GEMM_SMEM_BYTES);
    cudaFuncSetAttribute(attn_mma,
                         cudaFuncAttributeMaxDynamicSharedMemorySize,
                         ATTN_SMEM_BYTES);

    // 1) QKV projection -> q/k/v interleaved, q pre-scaled
    mma_gemm<<<dim3(QKV_N / 128, MROWS / 128), 256, GEMM_SMEM_BYTES>>>(
        b1, nullptr, QKV_N, 0);

    // 2) flash attention -> g_ctxh
    attn_mma<<<dim3(SEQ / 128, BATCH * NH), 128, ATTN_SMEM_BYTES>>>();

    // 3) output projection -> fp32 out
    mma_gemm<<<dim3(HID / 128, MROWS / 128), 256, GEMM_SMEM_BYTES>>>(
        b2, out, HID, 1);
}